// round 3
// baseline (speedup 1.0000x reference)
#include <cuda_runtime.h>
#include <cstdint>

#define IN_F  4096
#define OUT_F 4096
#define NTOK  8192
#define RANK  64

// ---------------- scratch (static device globals; no allocation) ----------------
__device__ float g_X  [(size_t)NTOK * IN_F];    // fwht'd, scaled, tf32-rounded input
__device__ float g_W  [(size_t)OUT_F * IN_F];   // dequantized codebook weights (tf32-rounded)
__device__ float g_Z  [(size_t)NTOK * OUT_F];   // x @ W^T
__device__ float g_ABX[(size_t)NTOK * OUT_F];   // (x B^T) A^T
__device__ float g_XB [NTOK * RANK];            // x @ B^T (tf32-rounded)
__device__ float g_XBp[4 * NTOK * RANK];        // split-K partials for XB
__device__ float g_AQ [OUT_F * RANK];           // tf32-rounded A
__device__ float g_C1 [IN_F];                   // SU / scaleWH

// ---------------- helpers ----------------
__device__ __forceinline__ float tf32r(float f) {
    uint32_t u;
    asm("cvt.rna.tf32.f32 %0, %1;" : "=r"(u) : "f"(f));
    return __uint_as_float(u);
}

#define BFLY(a, b) do { float _u = (a); float _v = (b); (a) = _u + _v; (b) = _u - _v; } while (0)

__device__ __forceinline__ void h8(float e[8]) {
    BFLY(e[0], e[1]); BFLY(e[2], e[3]); BFLY(e[4], e[5]); BFLY(e[6], e[7]);
    BFLY(e[0], e[2]); BFLY(e[1], e[3]); BFLY(e[4], e[6]); BFLY(e[5], e[7]);
    BFLY(e[0], e[4]); BFLY(e[1], e[5]); BFLY(e[2], e[6]); BFLY(e[3], e[7]);
}

// ---------------- tiny prep kernels ----------------
__global__ void c1_kernel(const float* __restrict__ SU, const float* __restrict__ sWH) {
    int i = blockIdx.x * 256 + threadIdx.x;
    if (i < IN_F) g_C1[i] = SU[i] / sWH[i];
}

__global__ void round_a_kernel(const float* __restrict__ A) {
    int i = blockIdx.x * 256 + threadIdx.x;
    if (i < OUT_F * RANK) g_AQ[i] = tf32r(A[i]);
}

// ---------------- dequant: W[m][k] = cb[Q[m][k/8]][k%8], tf32-rounded ----------------
__global__ void dequant_kernel(const int* __restrict__ Q, const float* __restrict__ cb) {
    int i = blockIdx.x * 256 + threadIdx.x;            // 0 .. 4096*512
    if (i >= OUT_F * (IN_F / 8)) return;
    int q = Q[i];
    const float4* c = reinterpret_cast<const float4*>(cb) + ((size_t)q << 1);
    float4 v0 = c[0], v1 = c[1];
    float4 r0, r1;
    r0.x = tf32r(v0.x); r0.y = tf32r(v0.y); r0.z = tf32r(v0.z); r0.w = tf32r(v0.w);
    r1.x = tf32r(v1.x); r1.y = tf32r(v1.y); r1.z = tf32r(v1.z); r1.w = tf32r(v1.w);
    float4* w = reinterpret_cast<float4*>(g_W) + ((size_t)i << 1);
    w[0] = r0; w[1] = r1;
}

// ---------------- FWHT pre: X = fwht(input * C1) / 64, tf32-rounded ----------------
__global__ void __launch_bounds__(512) fwht_pre(const float* __restrict__ in) {
    __shared__ float s[4608];
    int row = blockIdx.x;
    int t = threadIdx.x;
    const float* src = in + (size_t)row * IN_F;
    float e[8];

    // phase 1: bits 9..11 (stride 512)
#pragma unroll
    for (int i = 0; i < 8; i++) { int idx = t + (i << 9); e[i] = src[idx] * g_C1[idx]; }
    h8(e);
#pragma unroll
    for (int i = 0; i < 8; i++) { int idx = t + (i << 9); s[idx + (idx >> 3)] = e[i]; }
    __syncthreads();

    // phase 2: bits 6..8
    {
        int lo = t & 63, hi = t >> 6;
#pragma unroll
        for (int i = 0; i < 8; i++) { int idx = lo + (i << 6) + (hi << 9); e[i] = s[idx + (idx >> 3)]; }
        h8(e);
#pragma unroll
        for (int i = 0; i < 8; i++) { int idx = lo + (i << 6) + (hi << 9); s[idx + (idx >> 3)] = e[i]; }
    }
    __syncthreads();

    // phase 3: bits 3..5
    {
        int lo = t & 7, hi = t >> 3;
#pragma unroll
        for (int i = 0; i < 8; i++) { int idx = lo + (i << 3) + (hi << 6); e[i] = s[idx + (idx >> 3)]; }
        h8(e);
#pragma unroll
        for (int i = 0; i < 8; i++) { int idx = lo + (i << 3) + (hi << 6); s[idx + (idx >> 3)] = e[i]; }
    }
    __syncthreads();

    // phase 4: bits 0..2, scale, tf32-round, store
    {
#pragma unroll
        for (int i = 0; i < 8; i++) { int idx = (t << 3) + i; e[i] = s[idx + (idx >> 3)]; }
        h8(e);
        float4 o0, o1;
        o0.x = tf32r(e[0] * 0.015625f); o0.y = tf32r(e[1] * 0.015625f);
        o0.z = tf32r(e[2] * 0.015625f); o0.w = tf32r(e[3] * 0.015625f);
        o1.x = tf32r(e[4] * 0.015625f); o1.y = tf32r(e[5] * 0.015625f);
        o1.z = tf32r(e[6] * 0.015625f); o1.w = tf32r(e[7] * 0.015625f);
        float4* dst = reinterpret_cast<float4*>(g_X + (size_t)row * IN_F + (t << 3));
        dst[0] = o0; dst[1] = o1;
    }
}

// ---------------- FWHT post + epilogue: out = (fwht(Z)/64 + ABX) * SV + bias ----------------
__global__ void __launch_bounds__(512) fwht_post(const float* __restrict__ SV,
                                                 const float* __restrict__ bias,
                                                 float* __restrict__ out) {
    __shared__ float s[4608];
    int row = blockIdx.x;
    int t = threadIdx.x;
    const float* src = g_Z + (size_t)row * OUT_F;
    float e[8];

#pragma unroll
    for (int i = 0; i < 8; i++) { int idx = t + (i << 9); e[i] = src[idx]; }
    h8(e);
#pragma unroll
    for (int i = 0; i < 8; i++) { int idx = t + (i << 9); s[idx + (idx >> 3)] = e[i]; }
    __syncthreads();
    {
        int lo = t & 63, hi = t >> 6;
#pragma unroll
        for (int i = 0; i < 8; i++) { int idx = lo + (i << 6) + (hi << 9); e[i] = s[idx + (idx >> 3)]; }
        h8(e);
#pragma unroll
        for (int i = 0; i < 8; i++) { int idx = lo + (i << 6) + (hi << 9); s[idx + (idx >> 3)] = e[i]; }
    }
    __syncthreads();
    {
        int lo = t & 7, hi = t >> 3;
#pragma unroll
        for (int i = 0; i < 8; i++) { int idx = lo + (i << 3) + (hi << 6); e[i] = s[idx + (idx >> 3)]; }
        h8(e);
#pragma unroll
        for (int i = 0; i < 8; i++) { int idx = lo + (i << 3) + (hi << 6); s[idx + (idx >> 3)] = e[i]; }
    }
    __syncthreads();
    {
#pragma unroll
        for (int i = 0; i < 8; i++) { int idx = (t << 3) + i; e[i] = s[idx + (idx >> 3)]; }
        h8(e);
        int c0 = t << 3;
        const float4* abx = reinterpret_cast<const float4*>(g_ABX + (size_t)row * OUT_F + c0);
        const float4* sv  = reinterpret_cast<const float4*>(SV + c0);
        const float4* bs  = reinterpret_cast<const float4*>(bias + c0);
        float4 a0 = abx[0], a1 = abx[1];
        float4 s0 = sv[0],  s1 = sv[1];
        float4 b0 = bs[0],  b1 = bs[1];
        float4 o0, o1;
        o0.x = (e[0] * 0.015625f + a0.x) * s0.x + b0.x;
        o0.y = (e[1] * 0.015625f + a0.y) * s0.y + b0.y;
        o0.z = (e[2] * 0.015625f + a0.z) * s0.z + b0.z;
        o0.w = (e[3] * 0.015625f + a0.w) * s0.w + b0.w;
        o1.x = (e[4] * 0.015625f + a1.x) * s1.x + b1.x;
        o1.y = (e[5] * 0.015625f + a1.y) * s1.y + b1.y;
        o1.z = (e[6] * 0.015625f + a1.z) * s1.z + b1.z;
        o1.w = (e[7] * 0.015625f + a1.w) * s1.w + b1.w;
        float4* dst = reinterpret_cast<float4*>(out + (size_t)row * OUT_F + c0);
        dst[0] = o0; dst[1] = o1;
    }
}

// ---------------- XB = X @ B^T, split-K SIMT, deterministic partials ----------------
__global__ void __launch_bounds__(256) xb_partial(const float* __restrict__ B) {
    __shared__ float Xs[256][33];
    __shared__ float Bs[64][33];
    int bm = blockIdx.x;   // 0..31 (256 rows each)
    int ks = blockIdx.y;   // 0..3  (1024 K each)
    int tid = threadIdx.x;
    int ty = tid >> 3, tx = tid & 7;
    float acc[8][8];
#pragma unroll
    for (int i = 0; i < 8; i++)
#pragma unroll
        for (int j = 0; j < 8; j++) acc[i][j] = 0.f;

    int kbase = ks << 10;
    const float* Xg = g_X + (size_t)(bm * 256) * IN_F + kbase;
    const float* Bg = B + kbase;

    for (int kc = 0; kc < 1024; kc += 32) {
#pragma unroll
        for (int i = 0; i < 8; i++) {
            int f4 = tid + (i << 8);
            int r = f4 >> 3, c4 = (f4 & 7) << 2;
            float4 v = *reinterpret_cast<const float4*>(Xg + (size_t)r * IN_F + kc + c4);
            Xs[r][c4] = v.x; Xs[r][c4 + 1] = v.y; Xs[r][c4 + 2] = v.z; Xs[r][c4 + 3] = v.w;
        }
#pragma unroll
        for (int i = 0; i < 2; i++) {
            int f4 = tid + (i << 8);
            int r = f4 >> 3, c4 = (f4 & 7) << 2;
            float4 v = *reinterpret_cast<const float4*>(Bg + (size_t)r * IN_F + kc + c4);
            Bs[r][c4] = v.x; Bs[r][c4 + 1] = v.y; Bs[r][c4 + 2] = v.z; Bs[r][c4 + 3] = v.w;
        }
        __syncthreads();
#pragma unroll 4
        for (int k = 0; k < 32; k++) {
            float xr[8], br[8];
#pragma unroll
            for (int j = 0; j < 8; j++) xr[j] = Xs[ty * 8 + j][k];
#pragma unroll
            for (int j = 0; j < 8; j++) br[j] = Bs[tx * 8 + j][k];
#pragma unroll
            for (int jr = 0; jr < 8; jr++)
#pragma unroll
                for (int jc = 0; jc < 8; jc++) acc[jr][jc] += xr[jr] * br[jc];
        }
        __syncthreads();
    }
    float* dst = g_XBp + (size_t)ks * (NTOK * RANK) + (size_t)(bm * 256) * RANK;
#pragma unroll
    for (int jr = 0; jr < 8; jr++)
#pragma unroll
        for (int jc = 0; jc < 8; jc++)
            dst[(ty * 8 + jr) * RANK + tx * 8 + jc] = acc[jr][jc];
}

__global__ void xb_reduce() {
    int i = blockIdx.x * 256 + threadIdx.x;  // < 524288
    const int S = NTOK * RANK;
    float s = g_XBp[i] + g_XBp[i + S] + g_XBp[i + 2 * S] + g_XBp[i + 3 * S];
    g_XB[i] = tf32r(s);
}

// ---------------- tf32 mma GEMM: C[M,4096] = A[M,K] @ B[4096,K]^T (NT) ----------------
__device__ __forceinline__ void mma_tf32(float* c, const uint32_t* a, const uint32_t* b) {
    asm volatile(
        "mma.sync.aligned.m16n8k8.row.col.f32.tf32.tf32.f32 "
        "{%0,%1,%2,%3}, {%4,%5,%6,%7}, {%8,%9}, {%0,%1,%2,%3};\n"
        : "+f"(c[0]), "+f"(c[1]), "+f"(c[2]), "+f"(c[3])
        : "r"(a[0]), "r"(a[1]), "r"(a[2]), "r"(a[3]), "r"(b[0]), "r"(b[1]));
}

__device__ __forceinline__ void cp16(uint32_t s, const void* g) {
    asm volatile("cp.async.cg.shared.global [%0], [%1], 16;\n" :: "r"(s), "l"(g) : "memory");
}

__device__ __forceinline__ void load_tile(const float* g, int ldg, uint32_t sbase, int tid) {
    // 128 rows x 32 cols (floats), smem row stride 36
    int r = tid >> 3;
    int c4 = (tid & 7) << 2;
#pragma unroll
    for (int i = 0; i < 4; i++) {
        int row = r + (i << 5);
        cp16(sbase + (uint32_t)(row * 36 + c4) * 4u, g + (size_t)row * ldg + c4);
    }
}

#define GEMM_TB (128 * 36)
#define GEMM_SMEM (4 * GEMM_TB * 4)

__global__ void __launch_bounds__(256, 2) gemm_nt(const float* __restrict__ A,
                                                  const float* __restrict__ Bm,
                                                  float* __restrict__ C, int K) {
    extern __shared__ float sm[];
    uint32_t sA = (uint32_t)__cvta_generic_to_shared(sm);
    uint32_t sB = sA + 2u * GEMM_TB * 4u;
    int tid = threadIdx.x;
    const float* Ag = A + (size_t)(blockIdx.y * 128) * K;
    const float* Bg = Bm + (size_t)(blockIdx.x * 128) * K;
    int KIT = K >> 5;

    load_tile(Ag, K, sA, tid);
    load_tile(Bg, K, sB, tid);
    asm volatile("cp.async.commit_group;\n" ::: "memory");

    int lane = tid & 31, wid = tid >> 5;
    int g = lane >> 2, tg = lane & 3;
    int wm = (wid & 1) << 6;   // warp m offset: 2 warps in m
    int wn = (wid >> 1) << 5;  // warp n offset: 4 warps in n

    float acc[4][4][4];
#pragma unroll
    for (int a = 0; a < 4; a++)
#pragma unroll
        for (int b = 0; b < 4; b++)
#pragma unroll
            for (int c = 0; c < 4; c++) acc[a][b][c] = 0.f;

    const float* As = sm;
    const float* Bs = sm + 2 * GEMM_TB;

    for (int it = 0; it < KIT; it++) {
        if (it + 1 < KIT) {
            uint32_t nb = ((it + 1) & 1) ? (uint32_t)(GEMM_TB * 4) : 0u;
            load_tile(Ag + (it + 1) * 32, K, sA + nb, tid);
            load_tile(Bg + (it + 1) * 32, K, sB + nb, tid);
            asm volatile("cp.async.commit_group;\n" ::: "memory");
            asm volatile("cp.async.wait_group 1;\n" ::: "memory");
        } else {
            asm volatile("cp.async.wait_group 0;\n" ::: "memory");
        }
        __syncthreads();
        const float* Ac = As + (it & 1) * GEMM_TB;
        const float* Bc = Bs + (it & 1) * GEMM_TB;
#pragma unroll
        for (int ksu = 0; ksu < 4; ksu++) {
            int kc = ksu << 3;
            uint32_t af[4][4], bf[4][2];
#pragma unroll
            for (int mf = 0; mf < 4; mf++) {
                int r0 = wm + (mf << 4) + g;
                af[mf][0] = __float_as_uint(Ac[r0 * 36 + kc + tg]);
                af[mf][1] = __float_as_uint(Ac[(r0 + 8) * 36 + kc + tg]);
                af[mf][2] = __float_as_uint(Ac[r0 * 36 + kc + tg + 4]);
                af[mf][3] = __float_as_uint(Ac[(r0 + 8) * 36 + kc + tg + 4]);
            }
#pragma unroll
            for (int nf = 0; nf < 4; nf++) {
                int n0 = wn + (nf << 3) + g;
                bf[nf][0] = __float_as_uint(Bc[n0 * 36 + kc + tg]);
                bf[nf][1] = __float_as_uint(Bc[n0 * 36 + kc + tg + 4]);
            }
#pragma unroll
            for (int mf = 0; mf < 4; mf++)
#pragma unroll
                for (int nf = 0; nf < 4; nf++)
                    mma_tf32(acc[mf][nf], af[mf], bf[nf]);
        }
        __syncthreads();
    }

    int row0 = (blockIdx.y << 7) + wm + g;
    int col0 = (blockIdx.x << 7) + wn + (tg << 1);
#pragma unroll
    for (int mf = 0; mf < 4; mf++) {
#pragma unroll
        for (int nf = 0; nf < 4; nf++) {
            size_t r = (size_t)(row0 + (mf << 4));
            int c = col0 + (nf << 3);
            float2 v0 = make_float2(acc[mf][nf][0], acc[mf][nf][1]);
            float2 v1 = make_float2(acc[mf][nf][2], acc[mf][nf][3]);
            *reinterpret_cast<float2*>(C + r * 4096 + c) = v0;
            *reinterpret_cast<float2*>(C + (r + 8) * 4096 + c) = v1;
        }
    }
}

// ---------------- device-global-resident aliases for GEMM in/out ----------------
__global__ void gemm_z_launchdummy() {}  // (placeholder removed; direct launches below)

// ---------------- launch ----------------
extern "C" void kernel_launch(void* const* d_in, const int* in_sizes, int n_in,
                              void* d_out, int out_size) {
    const float* input   = (const float*)d_in[0];
    const int*   Qidxs   = (const int*)d_in[1];
    const float* cb      = (const float*)d_in[2];
    const float* SU      = (const float*)d_in[3];
    const float* SV      = (const float*)d_in[4];
    const float* A       = (const float*)d_in[5];
    const float* B       = (const float*)d_in[6];
    const float* scaleWH = (const float*)d_in[7];
    const float* bias    = (const float*)d_in[8];
    float* out = (float*)d_out;

    static bool attr_done = false;
    if (!attr_done) {
        if (cudaFuncSetAttribute(gemm_nt, cudaFuncAttributeMaxDynamicSharedMemorySize,
                                 GEMM_SMEM) == cudaSuccess)
            attr_done = true;
    }

    // Device pointers to scratch globals, resolved via a zero-cost trick:
    // kernels reference the globals directly; only gemm_nt needs raw pointers.
    // cudaGetSymbolAddress is capture-safe, but we avoid it: use helper kernels'
    // direct references for everything except gemm_nt, whose operands we pass
    // via small launch-time address fetch (host-side static cache).
    static float *X = nullptr, *W = nullptr, *Z = nullptr, *ABX = nullptr,
                 *XB = nullptr, *AQ = nullptr;
    if (!X) {
        cudaGetSymbolAddress((void**)&X,   g_X);
        cudaGetSymbolAddress((void**)&W,   g_W);
        cudaGetSymbolAddress((void**)&Z,   g_Z);
        cudaGetSymbolAddress((void**)&ABX, g_ABX);
        cudaGetSymbolAddress((void**)&XB,  g_XB);
        cudaGetSymbolAddress((void**)&AQ,  g_AQ);
    }

    c1_kernel<<<16, 256>>>(SU, scaleWH);
    fwht_pre<<<NTOK, 512>>>(input);
    dequant_kernel<<<(OUT_F * (IN_F / 8)) / 256, 256>>>(Qidxs, cb);
    round_a_kernel<<<(OUT_F * RANK) / 256, 256>>>(A);
    xb_partial<<<dim3(32, 4), 256>>>(B);
    xb_reduce<<<(NTOK * RANK) / 256, 256>>>();
    gemm_nt<<<dim3(32, 64), 256, GEMM_SMEM>>>(X, W, Z, IN_F);     // Z = X @ W^T
    gemm_nt<<<dim3(32, 64), 256, GEMM_SMEM>>>(XB, AQ, ABX, RANK); // ABX = XB @ A^T
    fwht_post<<<NTOK, 512>>>(SV, bias, out);
}